// round 14
// baseline (speedup 1.0000x reference)
#include <cuda_runtime.h>
#include <cuda_fp16.h>
#include <cstdint>

// Problem constants
#define NN   100000
#define EE   1600000
#define NPAD 100096              // padded rows; pads stay zero
#define NCHUNK 98                // ceil(NN / 1024)
#define NTILE 1563               // ceil(NN / 64)
#define GEMM_GRID 296            // 2 CTAs/SM * 148 SMs (persistent)

// ---------------------------------------------------------------------------
// Device scratch
// ---------------------------------------------------------------------------
__device__ int g_cnt[NN];                 // degree (histogram)
__device__ int g_off[NN];                 // CSR exclusive offsets
__device__ int g_pos[NN];                 // fill cursors
__device__ int g_csr[EE];                 // dst-grouped src indices
__device__ int g_chunksum[NCHUNK];
__device__ __half g_A1hi[NPAD * 256];     // [mean | x] pre-split fp16
__device__ __half g_A1lo[NPAD * 256];
__device__ float g_z[NN * 128];           // [ y (64) | y2 (64) ]
// Pre-split weights, [n][k] k-contiguous (hi plane only — 2-term scheme)
__device__ __half g_B1hi[128 * 256];
__device__ __half g_B2hi[128 * 128];

// ---------------------------------------------------------------------------
// Helpers
// ---------------------------------------------------------------------------
__device__ __forceinline__ uint32_t smem_u32(const void* p) {
    uint32_t a;
    asm("{ .reg .u64 t; cvta.to.shared.u64 t, %1; cvt.u32.u64 %0, t; }" : "=r"(a) : "l"(p));
    return a;
}
#define SWZ(o) ((o) ^ (((o) >> 3) & 0x70u))

__device__ __forceinline__ void split2h(float v, __half& h, __half& l) {
    h = __float2half_rn(v);
    l = __float2half_rn(v - __half2float(h));
}
__device__ __forceinline__ uint32_t pack_h(__half a, __half b) {
    __half2 t = __halves2half2(a, b);
    return *(uint32_t*)&t;
}

#define LDSM4(r, a) \
    asm volatile("ldmatrix.sync.aligned.m8n8.x4.shared.b16 {%0,%1,%2,%3}, [%4];" \
        : "=r"((r)[0]), "=r"((r)[1]), "=r"((r)[2]), "=r"((r)[3]) : "r"(a))

__device__ __forceinline__ void mma_f16(float* d, const uint32_t* a, uint32_t b0, uint32_t b1) {
    asm volatile("mma.sync.aligned.m16n8k16.row.col.f32.f16.f16.f32 "
                 "{%0,%1,%2,%3}, {%4,%5,%6,%7}, {%8,%9}, {%0,%1,%2,%3};"
                 : "+f"(d[0]), "+f"(d[1]), "+f"(d[2]), "+f"(d[3])
                 : "r"(a[0]), "r"(a[1]), "r"(a[2]), "r"(a[3]), "r"(b0), "r"(b1));
}

__device__ __forceinline__ void cp16(uint32_t s, const void* g) {
    asm volatile("cp.async.cg.shared.global [%0], [%1], 16;" :: "r"(s), "l"(g));
}
#define CP_COMMIT() asm volatile("cp.async.commit_group;" ::: "memory")
template <int N>
__device__ __forceinline__ void cp_wait() {
    asm volatile("cp.async.wait_group %0;" :: "n"(N) : "memory");
}

// ---------------------------------------------------------------------------
// prep_weights + zero degree counters (merged)
// ---------------------------------------------------------------------------
__global__ void prep_weights(const float* __restrict__ W1l, const float* __restrict__ W1r,
                             const float* __restrict__ W2l, const float* __restrict__ W2r) {
    int idx = blockIdx.x * blockDim.x + threadIdx.x;
    int stride = gridDim.x * blockDim.x;
    for (int i = idx; i < NN; i += stride) g_cnt[i] = 0;
    if (idx < 128 * 256) {
        int n = idx >> 8, k = idx & 255;
        float v = (k < 128) ? W1l[n * 128 + k] : W1r[n * 128 + (k - 128)];
        g_B1hi[idx] = __float2half_rn(v);
    }
    int idx2 = idx - 128 * 256;
    if (idx2 >= 0 && idx2 < 128 * 128) {
        int n = idx2 >> 7, k = idx2 & 127;
        float v = (n < 64) ? W2l[n * 128 + k] : W2r[(n - 64) * 128 + k];
        g_B2hi[idx2] = __float2half_rn(v);
    }
}

// ---------------------------------------------------------------------------
// CSR build
// ---------------------------------------------------------------------------
__global__ void count_deg(const int* __restrict__ ei) {
    int tid = blockIdx.x * blockDim.x + threadIdx.x;
    int stride = gridDim.x * blockDim.x;
    const int4* d4 = (const int4*)(ei + EE);
    for (int e = tid; e < EE / 4; e += stride) {
        int4 d = d4[e];
        atomicAdd(&g_cnt[d.x], 1);
        atomicAdd(&g_cnt[d.y], 1);
        atomicAdd(&g_cnt[d.z], 1);
        atomicAdd(&g_cnt[d.w], 1);
    }
}

__global__ void scan1() {   // grid = NCHUNK, 1024 threads
    __shared__ int wsum[32];
    int c = blockIdx.x, t = threadIdx.x;
    int i = c * 1024 + t;
    int v = (i < NN) ? g_cnt[i] : 0;
    int x = v;
#pragma unroll
    for (int o = 1; o < 32; o <<= 1) {
        int y = __shfl_up_sync(~0u, x, o);
        if ((t & 31) >= o) x += y;
    }
    if ((t & 31) == 31) wsum[t >> 5] = x;
    __syncthreads();
    if (t < 32) {
        int s = wsum[t];
#pragma unroll
        for (int o = 1; o < 32; o <<= 1) {
            int y = __shfl_up_sync(~0u, s, o);
            if (t >= o) s += y;
        }
        wsum[t] = s;
    }
    __syncthreads();
    int base = (t >= 32) ? wsum[(t >> 5) - 1] : 0;
    int incl = x + base;
    if (i < NN) g_off[i] = incl - v;
    if (t == 1023) g_chunksum[c] = incl;
}

__global__ void scan23() {
    __shared__ int excl[128];
    __shared__ int ws[4];
    int t = threadIdx.x;   // 256
    int v = 0, x = 0;
    if (t < 128) {
        v = (t < NCHUNK) ? g_chunksum[t] : 0;
        x = v;
#pragma unroll
        for (int o = 1; o < 32; o <<= 1) {
            int y = __shfl_up_sync(~0u, x, o);
            if ((t & 31) >= o) x += y;
        }
        if ((t & 31) == 31) ws[t >> 5] = x;
    }
    __syncthreads();
    if (t < 4) {
        int s = ws[t];
#pragma unroll
        for (int o = 1; o < 4; o <<= 1) {
            int y = __shfl_up_sync(0xFu, s, o);
            if (t >= o) s += y;
        }
        ws[t] = s;
    }
    __syncthreads();
    if (t < 128) {
        int base = (t >= 32) ? ws[(t >> 5) - 1] : 0;
        excl[t] = x + base - v;
    }
    __syncthreads();
    int tid = blockIdx.x * blockDim.x + t;
    int stride = gridDim.x * blockDim.x;
    for (int i = tid; i < NN; i += stride) {
        int o = g_off[i] + excl[i >> 10];
        g_off[i] = o;
        g_pos[i] = o;
    }
}

__global__ void fill_csr(const int* __restrict__ ei) {
    int tid = blockIdx.x * blockDim.x + threadIdx.x;
    int stride = gridDim.x * blockDim.x;
    const int4* s4 = (const int4*)ei;
    const int4* d4 = (const int4*)(ei + EE);
    for (int e = tid; e < EE / 4; e += stride) {
        int4 d = d4[e];
        int4 s = s4[e];
        g_csr[atomicAdd(&g_pos[d.x], 1)] = s.x;
        g_csr[atomicAdd(&g_pos[d.y], 1)] = s.y;
        g_csr[atomicAdd(&g_pos[d.z], 1)] = s.z;
        g_csr[atomicAdd(&g_pos[d.w], 1)] = s.w;
    }
}

// ---------------------------------------------------------------------------
// gather1: warp per node, unroll 8. Sum x[src] (fp32), mean, split fp16 ->
// A1 cols [0,128); split x[i] -> A1 cols [128,256).
// ---------------------------------------------------------------------------
__global__ void gather1(const float4* __restrict__ x4) {
    int lane = threadIdx.x & 31;
    int gw = (blockIdx.x * blockDim.x + threadIdx.x) >> 5;
    int nw = (gridDim.x * blockDim.x) >> 5;
    for (int i = gw; i < NN; i += nw) {
        int deg = g_cnt[i], start = g_off[i];
        float4 acc = make_float4(0.f, 0.f, 0.f, 0.f);
        int j = 0;
        for (; j + 8 <= deg; j += 8) {
            int s0 = g_csr[start + j],     s1 = g_csr[start + j + 1];
            int s2 = g_csr[start + j + 2], s3 = g_csr[start + j + 3];
            int s4 = g_csr[start + j + 4], s5 = g_csr[start + j + 5];
            int s6 = g_csr[start + j + 6], s7 = g_csr[start + j + 7];
            float4 v0 = x4[s0 * 32 + lane];
            float4 v1 = x4[s1 * 32 + lane];
            float4 v2 = x4[s2 * 32 + lane];
            float4 v3 = x4[s3 * 32 + lane];
            float4 v4 = x4[s4 * 32 + lane];
            float4 v5 = x4[s5 * 32 + lane];
            float4 v6 = x4[s6 * 32 + lane];
            float4 v7 = x4[s7 * 32 + lane];
            acc.x += ((v0.x + v1.x) + (v2.x + v3.x)) + ((v4.x + v5.x) + (v6.x + v7.x));
            acc.y += ((v0.y + v1.y) + (v2.y + v3.y)) + ((v4.y + v5.y) + (v6.y + v7.y));
            acc.z += ((v0.z + v1.z) + (v2.z + v3.z)) + ((v4.z + v5.z) + (v6.z + v7.z));
            acc.w += ((v0.w + v1.w) + (v2.w + v3.w)) + ((v4.w + v5.w) + (v6.w + v7.w));
        }
        for (; j + 4 <= deg; j += 4) {
            int s0 = g_csr[start + j],     s1 = g_csr[start + j + 1];
            int s2 = g_csr[start + j + 2], s3 = g_csr[start + j + 3];
            float4 v0 = x4[s0 * 32 + lane];
            float4 v1 = x4[s1 * 32 + lane];
            float4 v2 = x4[s2 * 32 + lane];
            float4 v3 = x4[s3 * 32 + lane];
            acc.x += (v0.x + v1.x) + (v2.x + v3.x);
            acc.y += (v0.y + v1.y) + (v2.y + v3.y);
            acc.z += (v0.z + v1.z) + (v2.z + v3.z);
            acc.w += (v0.w + v1.w) + (v2.w + v3.w);
        }
        for (; j < deg; j++) {
            int s = g_csr[start + j];
            float4 v = x4[s * 32 + lane];
            acc.x += v.x; acc.y += v.y; acc.z += v.z; acc.w += v.w;
        }
        float inv = 1.0f / fmaxf((float)deg, 1.0f);
        acc.x *= inv; acc.y *= inv; acc.z *= inv; acc.w *= inv;
        __half h0, h1, h2, h3, l0, l1, l2, l3;
        split2h(acc.x, h0, l0); split2h(acc.y, h1, l1);
        split2h(acc.z, h2, l2); split2h(acc.w, h3, l3);
        uint2 uh, ul;
        uh.x = pack_h(h0, h1); uh.y = pack_h(h2, h3);
        ul.x = pack_h(l0, l1); ul.y = pack_h(l2, l3);
        ((uint2*)g_A1hi)[(size_t)i * 64 + lane] = uh;
        ((uint2*)g_A1lo)[(size_t)i * 64 + lane] = ul;
        float4 xv = x4[i * 32 + lane];
        split2h(xv.x, h0, l0); split2h(xv.y, h1, l1);
        split2h(xv.z, h2, l2); split2h(xv.w, h3, l3);
        uh.x = pack_h(h0, h1); uh.y = pack_h(h2, h3);
        ul.x = pack_h(l0, l1); ul.y = pack_h(l2, l3);
        ((uint2*)g_A1hi)[(size_t)i * 64 + 32 + lane] = uh;
        ((uint2*)g_A1lo)[(size_t)i * 64 + 32 + lane] = ul;
    }
}

// ---------------------------------------------------------------------------
// FUSED layer1+layer2 GEMM, fp16 2-term, PERSISTENT (grid=296, tiles strided).
// 256 threads, CTA tile 64(M)x128(N), warp grid 2x4, 64KB smem, 2 CTAs/SM.
// Smem (64KB): buf c @ c*32768: A_HI +0, A_LO +8192, B1_HI +16384
//   overlaid after phase 1: B2 hi @ 0 + cc*16384; h hi @ 32768+cc*8192,
//   lo @ 49152+cc*8192.
// ---------------------------------------------------------------------------
__global__ __launch_bounds__(256, 2)
void gemm_fused(const float* __restrict__ b1) {
    constexpr int CH = 4;
    constexpr int BUFS = 32768;
    constexpr int A_HI = 0, A_LO = 8192, B_HI = 16384;
    constexpr int B2_HI = 0, H_HI = 32768, H_LO = 49152;
    extern __shared__ char sm[];
    const uint32_t sb = smem_u32(sm);
    const int tid = threadIdx.x, wid = tid >> 5, lane = tid & 31;
    const int wm = wid >> 2, wn = wid & 3;
    const int sub = lane >> 3, lr = lane & 7;

    for (int tile = blockIdx.x; tile < NTILE; tile += GEMM_GRID) {
        const int rowBase = tile * 64;

        auto load_chunk1 = [&](int c, int buf) {
            const uint32_t bb = sb + buf * BUFS;
#pragma unroll
            for (int it = 0; it < 2; it++) {
                int idx = it * 256 + tid;
                int row = idx >> 3, seg = idx & 7;
                uint32_t doff = SWZ((uint32_t)(row * 128 + seg * 16));
                size_t ga = (size_t)(rowBase + row) * 256 + c * 64 + seg * 8;
                cp16(bb + A_HI + doff, g_A1hi + ga);
                cp16(bb + A_LO + doff, g_A1lo + ga);
            }
#pragma unroll
            for (int it = 0; it < 4; it++) {
                int idx = it * 256 + tid;
                int row = idx >> 3, seg = idx & 7;
                uint32_t doff = SWZ((uint32_t)(row * 128 + seg * 16));
                size_t gb = (size_t)row * 256 + c * 64 + seg * 8;
                cp16(bb + B_HI + doff, g_B1hi + gb);
            }
        };

        auto load_B2 = [&]() {
#pragma unroll
            for (int it = 0; it < 8; it++) {
                int idx = it * 256 + tid;
                int cc  = idx >> 10;
                int r   = idx & 1023;
                int row = r >> 3, seg = r & 7;
                uint32_t doff = SWZ((uint32_t)(row * 128 + seg * 16));
                size_t gb = (size_t)row * 128 + cc * 64 + seg * 8;
                cp16(sb + B2_HI + cc * 16384 + doff, g_B2hi + gb);
            }
        };

        float acc[2][4][4];
#pragma unroll
        for (int i = 0; i < 2; i++)
#pragma unroll
            for (int j = 0; j < 4; j++)
#pragma unroll
                for (int r = 0; r < 4; r++) acc[i][j][r] = 0.f;

        load_chunk1(0, 0); CP_COMMIT();

        // ---- Phase 1 ----
        for (int c = 0; c < CH; c++) {
            if (c + 1 < CH) { load_chunk1(c + 1, (c + 1) & 1); CP_COMMIT(); cp_wait<1>(); }
            else            { load_B2(); CP_COMMIT(); cp_wait<1>(); }
            __syncthreads();

            const uint32_t bb = sb + (c & 1) * BUFS;
#pragma unroll
            for (int kk = 0; kk < 4; kk++) {
                uint32_t ah[2][4], al[2][4];
#pragma unroll
                for (int mi = 0; mi < 2; mi++) {
                    int row = wm * 32 + mi * 16 + (sub & 1) * 8 + lr;
                    int kb  = kk * 32 + (sub >> 1) * 16;
                    uint32_t off = SWZ((uint32_t)(row * 128 + kb));
                    LDSM4(ah[mi], bb + A_HI + off);
                    LDSM4(al[mi], bb + A_LO + off);
                }
#pragma unroll
                for (int p = 0; p < 2; p++) {
                    int nr = wn * 32 + p * 16 + (sub >> 1) * 8 + lr;
                    int kb = kk * 32 + (sub & 1) * 16;
                    uint32_t off = SWZ((uint32_t)(nr * 128 + kb));
                    uint32_t bh[4];
                    LDSM4(bh, bb + B_HI + off);
#pragma unroll
                    for (int mi = 0; mi < 2; mi++) {
#pragma unroll
                        for (int h = 0; h < 2; h++) {
                            float* d = acc[mi][p * 2 + h];
                            mma_f16(d, ah[mi], bh[2 * h], bh[2 * h + 1]);
                            mma_f16(d, al[mi], bh[2 * h], bh[2 * h + 1]);
                        }
                    }
                }
            }
            __syncthreads();
        }

        cp_wait<0>();   // B2 resident in buf0 region

        // ---- Epilogue 1: h = relu(acc + b1) -> split fp16 into h tiles ----
        {
#pragma unroll
            for (int mi = 0; mi < 2; mi++) {
#pragma unroll
                for (int p = 0; p < 2; p++) {
#pragma unroll
                    for (int h = 0; h < 2; h++) {
                        int col = wn * 32 + p * 16 + h * 8 + 2 * (lane & 3);
                        int cc = col >> 6, kin = col & 63;
                        float* d = acc[mi][p * 2 + h];
#pragma unroll
                        for (int half = 0; half < 2; half++) {
                            int row = wm * 32 + mi * 16 + (lane >> 2) + half * 8;
                            float v0 = fmaxf(d[half * 2 + 0] + b1[col], 0.f);
                            float v1 = fmaxf(d[half * 2 + 1] + b1[col + 1], 0.f);
                            __half h0, l0, h1, l1;
                            split2h(v0, h0, l0); split2h(v1, h1, l1);
                            uint32_t off = SWZ((uint32_t)(row * 128 + kin * 2));
                            *(uint32_t*)(sm + H_HI + cc * 8192 + off) = pack_h(h0, h1);
                            *(uint32_t*)(sm + H_LO + cc * 8192 + off) = pack_h(l0, l1);
                        }
                    }
                }
            }
        }
        __syncthreads();

        // ---- Phase 2: z = h @ B2 (K=128, smem-resident) ----
#pragma unroll
        for (int i = 0; i < 2; i++)
#pragma unroll
            for (int j = 0; j < 4; j++)
#pragma unroll
                for (int r = 0; r < 4; r++) acc[i][j][r] = 0.f;

#pragma unroll
        for (int cc = 0; cc < 2; cc++) {
            const uint32_t ahb = sb + H_HI + cc * 8192;
            const uint32_t alb = sb + H_LO + cc * 8192;
            const uint32_t bhb = sb + B2_HI + cc * 16384;
#pragma unroll
            for (int kk = 0; kk < 4; kk++) {
                uint32_t ah[2][4], al[2][4];
#pragma unroll
                for (int mi = 0; mi < 2; mi++) {
                    int row = wm * 32 + mi * 16 + (sub & 1) * 8 + lr;
                    int kb  = kk * 32 + (sub >> 1) * 16;
                    uint32_t off = SWZ((uint32_t)(row * 128 + kb));
                    LDSM4(ah[mi], ahb + off);
                    LDSM4(al[mi], alb + off);
                }
#pragma unroll
                for (int p = 0; p < 2; p++) {
                    int nr = wn * 32 + p * 16 + (sub >> 1) * 8 + lr;
                    int kb = kk * 32 + (sub & 1) * 16;
                    uint32_t off = SWZ((uint32_t)(nr * 128 + kb));
                    uint32_t bh[4];
                    LDSM4(bh, bhb + off);
#pragma unroll
                    for (int mi = 0; mi < 2; mi++) {
#pragma unroll
                        for (int h = 0; h < 2; h++) {
                            float* d = acc[mi][p * 2 + h];
                            mma_f16(d, ah[mi], bh[2 * h], bh[2 * h + 1]);
                            mma_f16(d, al[mi], bh[2 * h], bh[2 * h + 1]);
                        }
                    }
                }
            }
        }

        // ---- Epilogue 2: z -> global ----
#pragma unroll
        for (int mi = 0; mi < 2; mi++) {
            int r0 = rowBase + wm * 32 + mi * 16 + (lane >> 2);
#pragma unroll
            for (int p = 0; p < 2; p++) {
#pragma unroll
                for (int h = 0; h < 2; h++) {
                    int col = wn * 32 + p * 16 + h * 8 + 2 * (lane & 3);
                    float* d = acc[mi][p * 2 + h];
#pragma unroll
                    for (int half = 0; half < 2; half++) {
                        int gr = r0 + half * 8;
                        if (gr < NN) {
                            *(float2*)(g_z + (size_t)gr * 128 + col) =
                                make_float2(d[half * 2 + 0], d[half * 2 + 1]);
                        }
                    }
                }
            }
        }
        __syncthreads();   // all reads of B2/h done before next tile's loads
    }
}

// ---------------------------------------------------------------------------
// gather2 (+ fused finalize): warp per node, lane owns cols {2l, 2l+1},
// unroll 8. out[i] = mean_j(y[src_j]) + b2 + y2[i]
// ---------------------------------------------------------------------------
__global__ void gather2(float* __restrict__ out, const float* __restrict__ b2) {
    int lane = threadIdx.x & 31;
    int gw = (blockIdx.x * blockDim.x + threadIdx.x) >> 5;
    int nw = (gridDim.x * blockDim.x) >> 5;
    const float2* __restrict__ z2 = (const float2*)g_z;
    for (int i = gw; i < NN; i += nw) {
        int deg = g_cnt[i], start = g_off[i];
        float2 acc = make_float2(0.f, 0.f);
        int j = 0;
        for (; j + 8 <= deg; j += 8) {
            int s0 = g_csr[start + j],     s1 = g_csr[start + j + 1];
            int s2 = g_csr[start + j + 2], s3 = g_csr[start + j + 3];
            int s4 = g_csr[start + j + 4], s5 = g_csr[start + j + 5];
            int s6 = g_csr[start + j + 6], s7 = g_csr[start + j + 7];
            float2 v0 = z2[(size_t)s0 * 64 + lane];
            float2 v1 = z2[(size_t)s1 * 64 + lane];
            float2 v2 = z2[(size_t)s2 * 64 + lane];
            float2 v3 = z2[(size_t)s3 * 64 + lane];
            float2 v4 = z2[(size_t)s4 * 64 + lane];
            float2 v5 = z2[(size_t)s5 * 64 + lane];
            float2 v6 = z2[(size_t)s6 * 64 + lane];
            float2 v7 = z2[(size_t)s7 * 64 + lane];
            acc.x += ((v0.x + v1.x) + (v2.x + v3.x)) + ((v4.x + v5.x) + (v6.x + v7.x));
            acc.y += ((v0.y + v1.y) + (v2.y + v3.y)) + ((v4.y + v5.y) + (v6.y + v7.y));
        }
        for (; j + 4 <= deg; j += 4) {
            int s0 = g_csr[start + j],     s1 = g_csr[start + j + 1];
            int s2 = g_csr[start + j + 2], s3 = g_csr[start + j + 3];
            float2 v0 = z2[(size_t)s0 * 64 + lane];
            float2 v1 = z2[(size_t)s1 * 64 + lane];
            float2 v2 = z2[(size_t)s2 * 64 + lane];
            float2 v3 = z2[(size_t)s3 * 64 + lane];
            acc.x += (v0.x + v1.x) + (v2.x + v3.x);
            acc.y += (v0.y + v1.y) + (v2.y + v3.y);
        }
        for (; j < deg; j++) {
            int s = g_csr[start + j];
            float2 v = z2[(size_t)s * 64 + lane];
            acc.x += v.x; acc.y += v.y;
        }
        float inv = 1.0f / fmaxf((float)deg, 1.0f);
        float2 y2 = z2[(size_t)i * 64 + 32 + lane];
        float2 bb = ((const float2*)b2)[lane];
        float2 o = make_float2(acc.x * inv + bb.x + y2.x,
                               acc.y * inv + bb.y + y2.y);
        ((float2*)out)[(size_t)i * 32 + lane] = o;
    }
}

// ---------------------------------------------------------------------------
// Launch. Inputs: x, W1_l, W1_r, b1, W2_l, W2_r, b2, edge_index
// ---------------------------------------------------------------------------
extern "C" void kernel_launch(void* const* d_in, const int* in_sizes, int n_in,
                              void* d_out, int out_size) {
    const float* x   = (const float*)d_in[0];
    const float* W1l = (const float*)d_in[1];
    const float* W1r = (const float*)d_in[2];
    const float* b1  = (const float*)d_in[3];
    const float* W2l = (const float*)d_in[4];
    const float* W2r = (const float*)d_in[5];
    const float* b2  = (const float*)d_in[6];
    const int*   ei  = (const int*)d_in[7];
    float* out = (float*)d_out;

    const int SMEM = 65536;  // 64 KB -> 2 CTAs/SM
    cudaFuncSetAttribute(gemm_fused, cudaFuncAttributeMaxDynamicSharedMemorySize, SMEM);

    prep_weights<<<392, 256>>>(W1l, W1r, W2l, W2r);
    count_deg<<<1024, 256>>>(ei);
    scan1<<<NCHUNK, 1024>>>();
    scan23<<<392, 256>>>();
    fill_csr<<<1024, 256>>>(ei);
    gather1<<<2048, 256>>>((const float4*)x);
    gemm_fused<<<GEMM_GRID, 256, SMEM>>>(b1);
    gather2<<<2048, 256>>>(out, b2);
}

// round 15
// speedup vs baseline: 1.0999x; 1.0999x over previous
#include <cuda_runtime.h>
#include <cuda_fp16.h>
#include <cstdint>

// Problem constants
#define NN   100000
#define EE   1600000
#define NPAD 100096              // padded rows; pads stay zero
#define NCHUNK 98                // ceil(NN / 1024)

// ---------------------------------------------------------------------------
// Device scratch
// ---------------------------------------------------------------------------
__device__ int g_cnt[NN];                 // degree (histogram)
__device__ int g_off[NN];                 // CSR exclusive offsets
__device__ int g_pos[NN];                 // fill cursors
__device__ int g_csr[EE];                 // dst-grouped src indices
__device__ int g_chunksum[NCHUNK];
__device__ __half g_A1hi[NPAD * 256];     // [mean | x] pre-split fp16
__device__ __half g_A1lo[NPAD * 256];
__device__ float g_z[NN * 128];           // [ y (64) | y2 (64) ]
// Pre-split weights, [n][k] k-contiguous (hi plane only — 2-term scheme)
__device__ __half g_B1hi[128 * 256];
__device__ __half g_B2hi[128 * 128];

// ---------------------------------------------------------------------------
// Helpers
// ---------------------------------------------------------------------------
__device__ __forceinline__ uint32_t smem_u32(const void* p) {
    uint32_t a;
    asm("{ .reg .u64 t; cvta.to.shared.u64 t, %1; cvt.u32.u64 %0, t; }" : "=r"(a) : "l"(p));
    return a;
}
#define SWZ(o) ((o) ^ (((o) >> 3) & 0x70u))

__device__ __forceinline__ void split2h(float v, __half& h, __half& l) {
    h = __float2half_rn(v);
    l = __float2half_rn(v - __half2float(h));
}
__device__ __forceinline__ uint32_t pack_h(__half a, __half b) {
    __half2 t = __halves2half2(a, b);
    return *(uint32_t*)&t;
}

#define LDSM4(r, a) \
    asm volatile("ldmatrix.sync.aligned.m8n8.x4.shared.b16 {%0,%1,%2,%3}, [%4];" \
        : "=r"((r)[0]), "=r"((r)[1]), "=r"((r)[2]), "=r"((r)[3]) : "r"(a))

__device__ __forceinline__ void mma_f16(float* d, const uint32_t* a, uint32_t b0, uint32_t b1) {
    asm volatile("mma.sync.aligned.m16n8k16.row.col.f32.f16.f16.f32 "
                 "{%0,%1,%2,%3}, {%4,%5,%6,%7}, {%8,%9}, {%0,%1,%2,%3};"
                 : "+f"(d[0]), "+f"(d[1]), "+f"(d[2]), "+f"(d[3])
                 : "r"(a[0]), "r"(a[1]), "r"(a[2]), "r"(a[3]), "r"(b0), "r"(b1));
}

__device__ __forceinline__ void cp16(uint32_t s, const void* g) {
    asm volatile("cp.async.cg.shared.global [%0], [%1], 16;" :: "r"(s), "l"(g));
}
#define CP_COMMIT() asm volatile("cp.async.commit_group;" ::: "memory")
template <int N>
__device__ __forceinline__ void cp_wait() {
    asm volatile("cp.async.wait_group %0;" :: "n"(N) : "memory");
}

// ---------------------------------------------------------------------------
// prep_weights + zero degree counters (merged)
// ---------------------------------------------------------------------------
__global__ void prep_weights(const float* __restrict__ W1l, const float* __restrict__ W1r,
                             const float* __restrict__ W2l, const float* __restrict__ W2r) {
    int idx = blockIdx.x * blockDim.x + threadIdx.x;
    int stride = gridDim.x * blockDim.x;
    for (int i = idx; i < NN; i += stride) g_cnt[i] = 0;
    if (idx < 128 * 256) {
        int n = idx >> 8, k = idx & 255;
        float v = (k < 128) ? W1l[n * 128 + k] : W1r[n * 128 + (k - 128)];
        g_B1hi[idx] = __float2half_rn(v);
    }
    int idx2 = idx - 128 * 256;
    if (idx2 >= 0 && idx2 < 128 * 128) {
        int n = idx2 >> 7, k = idx2 & 127;
        float v = (n < 64) ? W2l[n * 128 + k] : W2r[(n - 64) * 128 + k];
        g_B2hi[idx2] = __float2half_rn(v);
    }
}

// ---------------------------------------------------------------------------
// CSR build
// ---------------------------------------------------------------------------
__global__ void count_deg(const int* __restrict__ ei) {
    int tid = blockIdx.x * blockDim.x + threadIdx.x;
    int stride = gridDim.x * blockDim.x;
    const int4* d4 = (const int4*)(ei + EE);
    for (int e = tid; e < EE / 4; e += stride) {
        int4 d = d4[e];
        atomicAdd(&g_cnt[d.x], 1);
        atomicAdd(&g_cnt[d.y], 1);
        atomicAdd(&g_cnt[d.z], 1);
        atomicAdd(&g_cnt[d.w], 1);
    }
}

__global__ void scan1() {   // grid = NCHUNK, 1024 threads
    __shared__ int wsum[32];
    int c = blockIdx.x, t = threadIdx.x;
    int i = c * 1024 + t;
    int v = (i < NN) ? g_cnt[i] : 0;
    int x = v;
#pragma unroll
    for (int o = 1; o < 32; o <<= 1) {
        int y = __shfl_up_sync(~0u, x, o);
        if ((t & 31) >= o) x += y;
    }
    if ((t & 31) == 31) wsum[t >> 5] = x;
    __syncthreads();
    if (t < 32) {
        int s = wsum[t];
#pragma unroll
        for (int o = 1; o < 32; o <<= 1) {
            int y = __shfl_up_sync(~0u, s, o);
            if (t >= o) s += y;
        }
        wsum[t] = s;
    }
    __syncthreads();
    int base = (t >= 32) ? wsum[(t >> 5) - 1] : 0;
    int incl = x + base;
    if (i < NN) g_off[i] = incl - v;
    if (t == 1023) g_chunksum[c] = incl;
}

__global__ void scan23() {
    __shared__ int excl[128];
    __shared__ int ws[4];
    int t = threadIdx.x;   // 256
    int v = 0, x = 0;
    if (t < 128) {
        v = (t < NCHUNK) ? g_chunksum[t] : 0;
        x = v;
#pragma unroll
        for (int o = 1; o < 32; o <<= 1) {
            int y = __shfl_up_sync(~0u, x, o);
            if ((t & 31) >= o) x += y;
        }
        if ((t & 31) == 31) ws[t >> 5] = x;
    }
    __syncthreads();
    if (t < 4) {
        int s = ws[t];
#pragma unroll
        for (int o = 1; o < 4; o <<= 1) {
            int y = __shfl_up_sync(0xFu, s, o);
            if (t >= o) s += y;
        }
        ws[t] = s;
    }
    __syncthreads();
    if (t < 128) {
        int base = (t >= 32) ? ws[(t >> 5) - 1] : 0;
        excl[t] = x + base - v;
    }
    __syncthreads();
    int tid = blockIdx.x * blockDim.x + t;
    int stride = gridDim.x * blockDim.x;
    for (int i = tid; i < NN; i += stride) {
        int o = g_off[i] + excl[i >> 10];
        g_off[i] = o;
        g_pos[i] = o;
    }
}

__global__ void fill_csr(const int* __restrict__ ei) {
    int tid = blockIdx.x * blockDim.x + threadIdx.x;
    int stride = gridDim.x * blockDim.x;
    const int4* s4 = (const int4*)ei;
    const int4* d4 = (const int4*)(ei + EE);
    for (int e = tid; e < EE / 4; e += stride) {
        int4 d = d4[e];
        int4 s = s4[e];
        g_csr[atomicAdd(&g_pos[d.x], 1)] = s.x;
        g_csr[atomicAdd(&g_pos[d.y], 1)] = s.y;
        g_csr[atomicAdd(&g_pos[d.z], 1)] = s.z;
        g_csr[atomicAdd(&g_pos[d.w], 1)] = s.w;
    }
}

// ---------------------------------------------------------------------------
// gather1: warp per node. Sum x[src] (fp32), mean, split fp16 -> A1 planes
// cols [0,128); split x[i] -> A1 planes cols [128,256).
// ---------------------------------------------------------------------------
__global__ void gather1(const float4* __restrict__ x4) {
    int lane = threadIdx.x & 31;
    int gw = (blockIdx.x * blockDim.x + threadIdx.x) >> 5;
    int nw = (gridDim.x * blockDim.x) >> 5;
    for (int i = gw; i < NN; i += nw) {
        int deg = g_cnt[i], start = g_off[i];
        float4 acc = make_float4(0.f, 0.f, 0.f, 0.f);
        int j = 0;
        for (; j + 4 <= deg; j += 4) {
            int s0 = g_csr[start + j], s1 = g_csr[start + j + 1];
            int s2 = g_csr[start + j + 2], s3 = g_csr[start + j + 3];
            float4 v0 = x4[s0 * 32 + lane];
            float4 v1 = x4[s1 * 32 + lane];
            float4 v2 = x4[s2 * 32 + lane];
            float4 v3 = x4[s3 * 32 + lane];
            acc.x += (v0.x + v1.x) + (v2.x + v3.x);
            acc.y += (v0.y + v1.y) + (v2.y + v3.y);
            acc.z += (v0.z + v1.z) + (v2.z + v3.z);
            acc.w += (v0.w + v1.w) + (v2.w + v3.w);
        }
        for (; j < deg; j++) {
            int s = g_csr[start + j];
            float4 v = x4[s * 32 + lane];
            acc.x += v.x; acc.y += v.y; acc.z += v.z; acc.w += v.w;
        }
        float inv = 1.0f / fmaxf((float)deg, 1.0f);
        acc.x *= inv; acc.y *= inv; acc.z *= inv; acc.w *= inv;
        __half h0, h1, h2, h3, l0, l1, l2, l3;
        split2h(acc.x, h0, l0); split2h(acc.y, h1, l1);
        split2h(acc.z, h2, l2); split2h(acc.w, h3, l3);
        uint2 uh, ul;
        uh.x = pack_h(h0, h1); uh.y = pack_h(h2, h3);
        ul.x = pack_h(l0, l1); ul.y = pack_h(l2, l3);
        ((uint2*)g_A1hi)[(size_t)i * 64 + lane] = uh;
        ((uint2*)g_A1lo)[(size_t)i * 64 + lane] = ul;
        float4 xv = x4[i * 32 + lane];
        split2h(xv.x, h0, l0); split2h(xv.y, h1, l1);
        split2h(xv.z, h2, l2); split2h(xv.w, h3, l3);
        uh.x = pack_h(h0, h1); uh.y = pack_h(h2, h3);
        ul.x = pack_h(l0, l1); ul.y = pack_h(l2, l3);
        ((uint2*)g_A1hi)[(size_t)i * 64 + 32 + lane] = uh;
        ((uint2*)g_A1lo)[(size_t)i * 64 + 32 + lane] = ul;
    }
}

// ---------------------------------------------------------------------------
// FUSED layer1+layer2 GEMM, fp16 2-term. 256 threads, CTA tile 64(M)x128(N),
// warp grid 2(M)x4(N), warp tile 32x32. 64KB smem -> 2 CTAs/SM.
// Smem (64KB):
//   buf c (c=0,1) @ c*32768: A_HI +0 (8K), A_LO +8192 (8K), B1_HI +16384 (16K)
//   After phase 1 (overlaid):
//     B2 hi  @ 0 + cc*16384          (into buf0; prefetched during chunk-3)
//     h  hi  @ 32768 + cc*8192, lo @ 49152 + cc*8192 (into buf1; epilogue-1)
// ---------------------------------------------------------------------------
__global__ __launch_bounds__(256, 2)
void gemm_fused(const float* __restrict__ b1) {
    constexpr int CH = 4;
    constexpr int BUFS = 32768;
    constexpr int A_HI = 0, A_LO = 8192, B_HI = 16384;
    constexpr int B2_HI = 0, H_HI = 32768, H_LO = 49152;
    extern __shared__ char sm[];
    const uint32_t sb = smem_u32(sm);
    const int tid = threadIdx.x, wid = tid >> 5, lane = tid & 31;
    const int rowBase = blockIdx.x * 64;
    const int wm = wid >> 2, wn = wid & 3;       // 2x4 warp grid
    const int sub = lane >> 3, lr = lane & 7;

    auto load_chunk1 = [&](int c, int buf) {
        const uint32_t bb = sb + buf * BUFS;
        // A planes: 512 segs of 16B each
#pragma unroll
        for (int it = 0; it < 2; it++) {
            int idx = it * 256 + tid;
            int row = idx >> 3, seg = idx & 7;       // row 0..63
            uint32_t doff = SWZ((uint32_t)(row * 128 + seg * 16));
            size_t ga = (size_t)(rowBase + row) * 256 + c * 64 + seg * 8;
            cp16(bb + A_HI + doff, g_A1hi + ga);
            cp16(bb + A_LO + doff, g_A1lo + ga);
        }
        // B1 hi: 1024 segs
#pragma unroll
        for (int it = 0; it < 4; it++) {
            int idx = it * 256 + tid;
            int row = idx >> 3, seg = idx & 7;       // row 0..127
            uint32_t doff = SWZ((uint32_t)(row * 128 + seg * 16));
            size_t gb = (size_t)row * 256 + c * 64 + seg * 8;
            cp16(bb + B_HI + doff, g_B1hi + gb);
        }
    };

    auto load_B2 = [&]() {
        // 2048 segs: cc chunks of 128 rows x 64 cols
#pragma unroll
        for (int it = 0; it < 8; it++) {
            int idx = it * 256 + tid;
            int cc  = idx >> 10;
            int r   = idx & 1023;
            int row = r >> 3, seg = r & 7;
            uint32_t doff = SWZ((uint32_t)(row * 128 + seg * 16));
            size_t gb = (size_t)row * 128 + cc * 64 + seg * 8;
            cp16(sb + B2_HI + cc * 16384 + doff, g_B2hi + gb);
        }
    };

    float acc[2][4][4];
#pragma unroll
    for (int i = 0; i < 2; i++)
#pragma unroll
        for (int j = 0; j < 4; j++)
#pragma unroll
            for (int r = 0; r < 4; r++) acc[i][j][r] = 0.f;

    load_chunk1(0, 0); CP_COMMIT();

    // ---- Phase 1 ----
    for (int c = 0; c < CH; c++) {
        if (c + 1 < CH) { load_chunk1(c + 1, (c + 1) & 1); CP_COMMIT(); cp_wait<1>(); }
        else            { load_B2(); CP_COMMIT(); cp_wait<1>(); }   // into buf0 (free)
        __syncthreads();

        const uint32_t bb = sb + (c & 1) * BUFS;
#pragma unroll
        for (int kk = 0; kk < 4; kk++) {
            uint32_t ah[2][4], al[2][4];
#pragma unroll
            for (int mi = 0; mi < 2; mi++) {
                int row = wm * 32 + mi * 16 + (sub & 1) * 8 + lr;     // 0..63
                int kb  = kk * 32 + (sub >> 1) * 16;
                uint32_t off = SWZ((uint32_t)(row * 128 + kb));
                LDSM4(ah[mi], bb + A_HI + off);
                LDSM4(al[mi], bb + A_LO + off);
            }
#pragma unroll
            for (int p = 0; p < 2; p++) {
                int nr = wn * 32 + p * 16 + (sub >> 1) * 8 + lr;      // 0..127
                int kb = kk * 32 + (sub & 1) * 16;
                uint32_t off = SWZ((uint32_t)(nr * 128 + kb));
                uint32_t bh[4];
                LDSM4(bh, bb + B_HI + off);
#pragma unroll
                for (int mi = 0; mi < 2; mi++) {
#pragma unroll
                    for (int h = 0; h < 2; h++) {
                        float* d = acc[mi][p * 2 + h];
                        mma_f16(d, ah[mi], bh[2 * h], bh[2 * h + 1]);
                        mma_f16(d, al[mi], bh[2 * h], bh[2 * h + 1]);
                    }
                }
            }
        }
        __syncthreads();
    }

    cp_wait<0>();   // B2 resident in buf0 region

    // ---- Epilogue 1: h = relu(acc + b1) -> split fp16 into h tiles (buf1) ----
    {
#pragma unroll
        for (int mi = 0; mi < 2; mi++) {
#pragma unroll
            for (int p = 0; p < 2; p++) {
#pragma unroll
                for (int h = 0; h < 2; h++) {
                    int col = wn * 32 + p * 16 + h * 8 + 2 * (lane & 3);
                    int cc = col >> 6, kin = col & 63;
                    float* d = acc[mi][p * 2 + h];
#pragma unroll
                    for (int half = 0; half < 2; half++) {
                        int row = wm * 32 + mi * 16 + (lane >> 2) + half * 8;  // 0..63
                        float v0 = fmaxf(d[half * 2 + 0] + b1[col], 0.f);
                        float v1 = fmaxf(d[half * 2 + 1] + b1[col + 1], 0.f);
                        __half h0, l0, h1, l1;
                        split2h(v0, h0, l0); split2h(v1, h1, l1);
                        uint32_t off = SWZ((uint32_t)(row * 128 + kin * 2));
                        *(uint32_t*)(sm + H_HI + cc * 8192 + off) = pack_h(h0, h1);
                        *(uint32_t*)(sm + H_LO + cc * 8192 + off) = pack_h(l0, l1);
                    }
                }
            }
        }
    }
    __syncthreads();

    // ---- Phase 2: z = h @ B2 (K=128, 2 chunks, smem-resident) ----
#pragma unroll
    for (int i = 0; i < 2; i++)
#pragma unroll
        for (int j = 0; j < 4; j++)
#pragma unroll
            for (int r = 0; r < 4; r++) acc[i][j][r] = 0.f;

#pragma unroll
    for (int cc = 0; cc < 2; cc++) {
        const uint32_t ahb = sb + H_HI + cc * 8192;
        const uint32_t alb = sb + H_LO + cc * 8192;
        const uint32_t bhb = sb + B2_HI + cc * 16384;
#pragma unroll
        for (int kk = 0; kk < 4; kk++) {
            uint32_t ah[2][4], al[2][4];
#pragma unroll
            for (int mi = 0; mi < 2; mi++) {
                int row = wm * 32 + mi * 16 + (sub & 1) * 8 + lr;     // 0..63
                int kb  = kk * 32 + (sub >> 1) * 16;
                uint32_t off = SWZ((uint32_t)(row * 128 + kb));
                LDSM4(ah[mi], ahb + off);
                LDSM4(al[mi], alb + off);
            }
#pragma unroll
            for (int p = 0; p < 2; p++) {
                int nr = wn * 32 + p * 16 + (sub >> 1) * 8 + lr;      // 0..127
                int kb = kk * 32 + (sub & 1) * 16;
                uint32_t off = SWZ((uint32_t)(nr * 128 + kb));
                uint32_t bh[4];
                LDSM4(bh, bhb + off);
#pragma unroll
                for (int mi = 0; mi < 2; mi++) {
#pragma unroll
                    for (int h = 0; h < 2; h++) {
                        float* d = acc[mi][p * 2 + h];
                        mma_f16(d, ah[mi], bh[2 * h], bh[2 * h + 1]);
                        mma_f16(d, al[mi], bh[2 * h], bh[2 * h + 1]);
                    }
                }
            }
        }
    }

    // ---- Epilogue 2: z -> global ----
#pragma unroll
    for (int mi = 0; mi < 2; mi++) {
        int r0 = rowBase + wm * 32 + mi * 16 + (lane >> 2);
#pragma unroll
        for (int p = 0; p < 2; p++) {
#pragma unroll
            for (int h = 0; h < 2; h++) {
                int col = wn * 32 + p * 16 + h * 8 + 2 * (lane & 3);
                float* d = acc[mi][p * 2 + h];
#pragma unroll
                for (int half = 0; half < 2; half++) {
                    int gr = r0 + half * 8;
                    if (gr < NN) {
                        *(float2*)(g_z + (size_t)gr * 128 + col) =
                            make_float2(d[half * 2 + 0], d[half * 2 + 1]);
                    }
                }
            }
        }
    }
}

// ---------------------------------------------------------------------------
// gather2 (+ fused finalize): warp per node, lane owns cols {2l, 2l+1}.
// out[i] = mean_j(y[src_j]) + b2 + y2[i]
// ---------------------------------------------------------------------------
__global__ void gather2(float* __restrict__ out, const float* __restrict__ b2) {
    int lane = threadIdx.x & 31;
    int gw = (blockIdx.x * blockDim.x + threadIdx.x) >> 5;
    int nw = (gridDim.x * blockDim.x) >> 5;
    const float2* __restrict__ z2 = (const float2*)g_z;
    for (int i = gw; i < NN; i += nw) {
        int deg = g_cnt[i], start = g_off[i];
        float2 acc = make_float2(0.f, 0.f);
        int j = 0;
        for (; j + 4 <= deg; j += 4) {
            int s0 = g_csr[start + j], s1 = g_csr[start + j + 1];
            int s2 = g_csr[start + j + 2], s3 = g_csr[start + j + 3];
            float2 v0 = z2[(size_t)s0 * 64 + lane];
            float2 v1 = z2[(size_t)s1 * 64 + lane];
            float2 v2 = z2[(size_t)s2 * 64 + lane];
            float2 v3 = z2[(size_t)s3 * 64 + lane];
            acc.x += (v0.x + v1.x) + (v2.x + v3.x);
            acc.y += (v0.y + v1.y) + (v2.y + v3.y);
        }
        for (; j < deg; j++) {
            int s = g_csr[start + j];
            float2 v = z2[(size_t)s * 64 + lane];
            acc.x += v.x; acc.y += v.y;
        }
        float inv = 1.0f / fmaxf((float)deg, 1.0f);
        float2 y2 = z2[(size_t)i * 64 + 32 + lane];
        float2 bb = ((const float2*)b2)[lane];
        float2 o = make_float2(acc.x * inv + bb.x + y2.x,
                               acc.y * inv + bb.y + y2.y);
        ((float2*)out)[(size_t)i * 32 + lane] = o;
    }
}

// ---------------------------------------------------------------------------
// Launch. Inputs: x, W1_l, W1_r, b1, W2_l, W2_r, b2, edge_index
// ---------------------------------------------------------------------------
extern "C" void kernel_launch(void* const* d_in, const int* in_sizes, int n_in,
                              void* d_out, int out_size) {
    const float* x   = (const float*)d_in[0];
    const float* W1l = (const float*)d_in[1];
    const float* W1r = (const float*)d_in[2];
    const float* b1  = (const float*)d_in[3];
    const float* W2l = (const float*)d_in[4];
    const float* W2r = (const float*)d_in[5];
    const float* b2  = (const float*)d_in[6];
    const int*   ei  = (const int*)d_in[7];
    float* out = (float*)d_out;

    const int SMEM = 65536;  // 64 KB -> 2 CTAs/SM
    cudaFuncSetAttribute(gemm_fused, cudaFuncAttributeMaxDynamicSharedMemorySize, SMEM);

    const int NBLK = (NN + 63) / 64;  // 1563

    prep_weights<<<392, 256>>>(W1l, W1r, W2l, W2r);
    count_deg<<<1024, 256>>>(ei);
    scan1<<<NCHUNK, 1024>>>();
    scan23<<<392, 256>>>();
    fill_csr<<<1024, 256>>>(ei);
    gather1<<<2048, 256>>>((const float4*)x);
    gemm_fused<<<NBLK, 256, SMEM>>>(b1);
    gather2<<<2048, 256>>>(out, b2);
}